// round 17
// baseline (speedup 1.0000x reference)
#include <cuda_runtime.h>
#include <cuda_bf16.h>
#include <cstdint>
#include <float.h>
#include <math.h>

#define BATCH 4
#define HW    4096
#define CDIM  256
#define NSTRIP 32
#define NPAIR  528
#define EPSQ  1e-9f
#define TLC   0.6f
#define LC    2.0f
#define SCALE 23.0f
#define MARGIN 3.3f               // covers int8 quant error (~5.5 sigma) + trunc
#define VMASK 0xFFFFC000u         // 18-bit value field (low 14 bits = row|col)
#define CHB   16384               // one 128x128 int8 chunk (128B rows, XOR swizzled)
#define BUFB  (2 * CHB)           // A chunk + B chunk per buffer
#define TOTSMEM (2 * BUFB)        // 65536 B double-buffered (Dt aliases all)
#define DPW   128                 // D-tile words per row (XOR-swizzled blocks)

// static scratch. g_x8 layout: [b][strip][kc(2)][chunk 16KB], swizzle baked.
__device__ __align__(128) char g_x8[BATCH * HW * CDIM];
__device__ float    g_norms[BATCH * HW];     // fp32 norms (refinement)
__device__ int      g_normsq[BATCH * HW];    // int norms of quantized rows
__device__ uint32_t g_pc[(size_t)BATCH * HW * NSTRIP * 8];  // top-8 keys/slot
__device__ int      g_flagcnt;
__device__ int      g_flaglist[BATCH * HW];

// ---------------------------------------------------------------------------
__device__ __forceinline__ uint32_t smem_u32(const void* p) {
    uint32_t a;
    asm("{ .reg .u64 t; cvta.to.shared.u64 t, %1; cvt.u32.u64 %0, t; }"
        : "=r"(a) : "l"(p));
    return a;
}
__device__ __forceinline__ void ldsm_x4(uint32_t (&r)[4], uint32_t addr) {
    asm volatile("ldmatrix.sync.aligned.m8n8.x4.shared.b16 {%0,%1,%2,%3}, [%4];"
                 : "=r"(r[0]), "=r"(r[1]), "=r"(r[2]), "=r"(r[3]) : "r"(addr));
}
__device__ __forceinline__ uint32_t redux_min_u32(uint32_t v) {
    uint32_t r;
    asm volatile("redux.sync.min.u32 %0, %1, 0xffffffff;" : "=r"(r) : "r"(v));
    return r;
}
#define MMA16832(d, a, b0_, b1_)                                                 \
    asm volatile("mma.sync.aligned.m16n8k32.row.col.s32.s8.s8.s32 "              \
                 "{%0,%1,%2,%3}, {%4,%5,%6,%7}, {%8,%9}, {%0,%1,%2,%3};"         \
                 : "+r"((d)[0]), "+r"((d)[1]), "+r"((d)[2]), "+r"((d)[3])        \
                 : "r"((a)[0]), "r"((a)[1]), "r"((a)[2]), "r"((a)[3]),           \
                   "r"(b0_), "r"(b1_))

#define MBARRIER_INIT(mbar, cnt) \
    asm volatile("mbarrier.init.shared.b64 [%0], %1;" \
                 :: "r"((uint32_t)(mbar)), "r"((uint32_t)(cnt)) : "memory")
#define MBARRIER_EXPECT_TX(mbar, tx) \
    asm volatile("mbarrier.arrive.expect_tx.shared.b64 _, [%0], %1;" \
                 :: "r"((uint32_t)(mbar)), "r"((uint32_t)(tx)) : "memory")
#define MBARRIER_WAIT_PARITY(mbar, parity) do {                                     \
    uint32_t _m = (uint32_t)(mbar); uint32_t _p = (uint32_t)(parity);               \
    asm volatile("{\n .reg .pred P1;\n"                                             \
                 "WAIT_LOOP_%=:\n"                                                  \
                 " mbarrier.try_wait.parity.acquire.cta.shared::cta.b64 P1,[%0],%1,0x989680;\n" \
                 " @P1 bra.uni WAIT_DONE_%=;\n"                                     \
                 " bra.uni WAIT_LOOP_%=;\n"                                         \
                 "WAIT_DONE_%=:\n}"                                                 \
                 :: "r"(_m), "r"(_p) : "memory");                                   \
} while (0)
#define BULK_G2S(dst, src, bytes, mbar) \
    asm volatile("cp.async.bulk.shared::cta.global.mbarrier::complete_tx::bytes " \
                 "[%0], [%1], %2, [%3];" \
                 :: "r"((uint32_t)(dst)), "l"(src), "r"((uint32_t)(bytes)), \
                    "r"((uint32_t)(mbar)) : "memory")

__device__ __forceinline__ bool ltp(float av, int ai, float bv, int bi) {
    return (av < bv) || (av == bv && ai < bi);
}
__device__ __forceinline__ void ceu(uint32_t& a, uint32_t& b) {
    uint32_t mn = min(a, b);
    b = max(a, b);
    a = mn;
}
__device__ __forceinline__ void sort4u(uint32_t (&k)[4]) {
    ceu(k[0], k[1]); ceu(k[2], k[3]);
    ceu(k[0], k[2]); ceu(k[1], k[3]);
    ceu(k[1], k[2]);
}
__device__ __forceinline__ float predict(float m1, float m2) {
    float d1 = sqrtf(fmaxf(m1, 0.f) + EPSQ);
    float d2 = sqrtf(fmaxf(m2, 0.f) + EPSQ);
    float e  = expf(d1);
    return (d1 / d2 < TLC) ? 2.f / (1.f + e) : 2.f / (1.f + LC * e);
}

// ---------------------------------------------------------------------------
// Kernel 1: int8 quantize (to swizzled chunk layout) + int/fp32 row norms.
// Two rows per warp; lane covers 8 floats: chunk kc = lane>>4, 8B half.
// ---------------------------------------------------------------------------
__global__ void convert_norms_kernel(const float* __restrict__ x) {
    if (blockIdx.x == 0 && threadIdx.x == 0) g_flagcnt = 0;
    int warp = (blockIdx.x * blockDim.x + threadIdx.x) >> 5;  // 0..8191
    int lane = threadIdx.x & 31;
    int gw0 = warp * 2;

    const int kc = lane >> 4;
    const int gg = (lane & 15) >> 1;
    const int hf = lane & 1;

    #pragma unroll
    for (int rr = 0; rr < 2; ++rr) {
        const int gw = gw0 + rr;
        const float* xr = x + (size_t)gw * CDIM + lane * 8;
        float4 v0 = *(const float4*)xr;
        float4 v1 = *(const float4*)(xr + 4);

        float sf = v0.x*v0.x + v0.y*v0.y + v0.z*v0.z + v0.w*v0.w
                 + v1.x*v1.x + v1.y*v1.y + v1.z*v1.z + v1.w*v1.w;

        int q[8];
        q[0] = __float2int_rn(v0.x * SCALE); q[1] = __float2int_rn(v0.y * SCALE);
        q[2] = __float2int_rn(v0.z * SCALE); q[3] = __float2int_rn(v0.w * SCALE);
        q[4] = __float2int_rn(v1.x * SCALE); q[5] = __float2int_rn(v1.y * SCALE);
        q[6] = __float2int_rn(v1.z * SCALE); q[7] = __float2int_rn(v1.w * SCALE);
        int si = 0;
        #pragma unroll
        for (int t = 0; t < 8; ++t) {
            q[t] = max(-127, min(127, q[t]));
            si += q[t] * q[t];
        }
        uint2 pk;
        pk.x = (uint32_t)(q[0] & 0xFF) | ((uint32_t)(q[1] & 0xFF) << 8)
             | ((uint32_t)(q[2] & 0xFF) << 16) | ((uint32_t)(q[3] & 0xFF) << 24);
        pk.y = (uint32_t)(q[4] & 0xFF) | ((uint32_t)(q[5] & 0xFF) << 8)
             | ((uint32_t)(q[6] & 0xFF) << 16) | ((uint32_t)(q[7] & 0xFF) << 24);

        const int r = gw & 127;
        char* dst = g_x8 + (size_t)(((gw >> 7) * 2) + kc) * CHB
                  + (size_t)(r * 128 + ((gg ^ (r & 7)) << 4) + hf * 8);
        *(uint2*)dst = pk;

        // int norm via redux.add; fp32 norm via shfl chain
        uint32_t st;
        asm volatile("redux.sync.add.u32 %0, %1, 0xffffffff;"
                     : "=r"(st) : "r"((uint32_t)si));
        #pragma unroll
        for (int o = 16; o; o >>= 1) sf += __shfl_xor_sync(0xffffffffu, sf, o);
        if (lane == 0) { g_normsq[gw] = (int)st; g_norms[gw] = sf; }
    }
}

// ---------------------------------------------------------------------------
// Kernel 2: single-pass s8 Gram tile-pair (exact integer quantized distances),
// bulk-async staging, packed dual-index keys, top-8 per row/col via redux.
// ---------------------------------------------------------------------------
__global__ __launch_bounds__(512, 2)
void fcm_pair_kernel() {
    extern __shared__ __align__(128) char smem[];
    __shared__ __align__(8) unsigned long long s_mbar[2];
    const uint32_t sbase = smem_u32(smem);
    const uint32_t mb0 = smem_u32(&s_mbar[0]);
    const uint32_t mb1 = smem_u32(&s_mbar[1]);

    const int tid  = threadIdx.x;
    const int lane = tid & 31;
    const int w    = tid >> 5;
    const int mw   = w >> 2;
    const int nw   = w & 3;
    const int b    = blockIdx.y;

    int p = blockIdx.x;
    int i = (int)((65.0f - sqrtf(4225.0f - 8.0f * (float)p)) * 0.5f);
    while ((i + 1) * (65 - (i + 1)) / 2 <= p) ++i;
    while (i * (65 - i) / 2 > p) --i;
    const int j = i + (p - i * (65 - i) / 2);
    const int row0 = i * 128, col0 = j * 128;
    const bool diag = (i == j);

    const char* xch = g_x8 + (size_t)b * (NSTRIP * 2) * CHB;
    const int lrow = ((lane >> 3) & 1) * 8 + (lane & 7);
    const int hi16 = lane >> 4;

    if (tid == 0) { MBARRIER_INIT(mb0, 1); MBARRIER_INIT(mb1, 1); }
    __syncthreads();

    auto stage = [&](int kc) {    // tid==0 only
        const int buf = kc & 1;
        const uint32_t mb = buf ? mb1 : mb0;
        const uint32_t dst = sbase + (uint32_t)(buf * BUFB);
        MBARRIER_EXPECT_TX(mb, diag ? CHB : 2 * CHB);
        BULK_G2S(dst, xch + (size_t)(i * 2 + kc) * CHB, CHB, mb);
        if (!diag)
            BULK_G2S(dst + CHB, xch + (size_t)(j * 2 + kc) * CHB, CHB, mb);
    };
    if (tid == 0) stage(0);

    int acc[2][4][4];
    #pragma unroll
    for (int mf = 0; mf < 2; ++mf)
        #pragma unroll
        for (int nf = 0; nf < 4; ++nf)
            #pragma unroll
            for (int e = 0; e < 4; ++e) acc[mf][nf][e] = 0;

    int ph0 = 0, ph1 = 0;
    for (int kc = 0; kc < 2; ++kc) {
        if (kc & 1) { MBARRIER_WAIT_PARITY(mb1, ph1); ph1 ^= 1; }
        else        { MBARRIER_WAIT_PARITY(mb0, ph0); ph0 ^= 1; }
        __syncthreads();
        if (kc < 1 && tid == 0) stage(kc + 1);

        const uint32_t abase = sbase + (uint32_t)((kc & 1) * BUFB);
        const uint32_t bbase = diag ? abase : abase + CHB;
        const int ra = mw * 32 + lrow;
        const int rb = nw * 32 + lrow;
        const uint32_t am = (uint32_t)(lrow & 7);
        #pragma unroll
        for (int ks = 0; ks < 4; ++ks) {            // 4 x k32 per chunk
            const uint32_t goff = (((uint32_t)(ks * 2 + hi16) ^ am) << 4);
            uint32_t ah[2][4], bh[2][4];
            ldsm_x4(ah[0], abase + (uint32_t)(ra * 128) + goff);
            ldsm_x4(ah[1], abase + (uint32_t)((ra + 16) * 128) + goff);
            ldsm_x4(bh[0], bbase + (uint32_t)(rb * 128) + goff);
            ldsm_x4(bh[1], bbase + (uint32_t)((rb + 16) * 128) + goff);
            #pragma unroll
            for (int mf = 0; mf < 2; ++mf)
                #pragma unroll
                for (int nf = 0; nf < 4; ++nf)
                    MMA16832(acc[mf][nf], ah[mf],
                             bh[nf >> 1][nf & 1], bh[nf >> 1][(nf & 1) + 2]);
        }
    }
    __syncthreads();                 // ldsm done; alias smem as key D-tile

    // ---- packed dual-index keys (exact int distances) into swizzled SMEM ----
    // word(r,c) = r*128 + ((c>>2 ^ (r&31))<<2) + ((c&3) ^ ((r>>3)&3))
    uint32_t* Dt = (uint32_t*)smem;
    #pragma unroll
    for (int mf = 0; mf < 2; ++mf) {
        const int r0l = mw * 32 + mf * 16 + (lane >> 2);
        const int r1l = r0l + 8;
        const int na0 = g_normsq[b * HW + row0 + r0l];
        const int na1 = g_normsq[b * HW + row0 + r1l];
        const int* nqp = g_normsq + b * HW + col0 + nw * 32 + (lane & 3) * 2;
        const int v0 = (r0l >> 3) & 3;
        const int v1 = (r1l >> 3) & 3;
        #pragma unroll
        for (int nf = 0; nf < 4; ++nf) {
            int2 nb = *(const int2*)(nqp + nf * 8);
            const int cl = nw * 32 + nf * 8 + (lane & 3) * 2;
            const int cb = cl >> 2, cq = cl & 3;
            uint32_t d00 = (uint32_t)(na0 + nb.x - 2 * acc[mf][nf][0]);
            uint32_t d01 = (uint32_t)(na0 + nb.y - 2 * acc[mf][nf][1]);
            uint32_t d10 = (uint32_t)(na1 + nb.x - 2 * acc[mf][nf][2]);
            uint32_t d11 = (uint32_t)(na1 + nb.y - 2 * acc[mf][nf][3]);
            uint32_t k00 = ((d00 << 8) & VMASK) | ((uint32_t)r0l << 7) | (uint32_t)cl;
            uint32_t k01 = ((d01 << 8) & VMASK) | ((uint32_t)r0l << 7) | (uint32_t)(cl + 1);
            uint32_t k10 = ((d10 << 8) & VMASK) | ((uint32_t)r1l << 7) | (uint32_t)cl;
            uint32_t k11 = ((d11 << 8) & VMASK) | ((uint32_t)r1l << 7) | (uint32_t)(cl + 1);
            if (diag) {
                if (r0l == cl)     k00 = 0xFFFFFFFFu;
                if (r0l == cl + 1) k01 = 0xFFFFFFFFu;
                if (r1l == cl)     k10 = 0xFFFFFFFFu;
                if (r1l == cl + 1) k11 = 0xFFFFFFFFu;
            }
            const int base0 = r0l * DPW + ((cb ^ (r0l & 31)) << 2) + (cq ^ (v0 & 2));
            const int base1 = r1l * DPW + ((cb ^ (r1l & 31)) << 2) + (cq ^ (v1 & 2));
            *(uint2*)&Dt[base0] = (v0 & 1) ? make_uint2(k01, k00)
                                           : make_uint2(k00, k01);
            *(uint2*)&Dt[base1] = (v1 & 1) ? make_uint2(k11, k10)
                                           : make_uint2(k10, k11);
        }
    }
    __syncthreads();

    // ---- top-8 extraction: 2 tasks/iter, 8 redux pops ----
    const uint32_t vlo = (uint32_t)((lane >> 3) & 3);
    const int ntask = diag ? 128 : 256;
    for (int t0 = w; t0 < ntask; t0 += 32) {
        uint32_t k[2][4];
        bool isrow[2];
        #pragma unroll
        for (int u = 0; u < 2; ++u) {
            const int t = t0 + 16 * u;
            isrow[u] = (t < 128);
            if (isrow[u]) {
                const int rr = t;
                const uint4 dv =
                    *(const uint4*)&Dt[rr * DPW + ((lane ^ (rr & 31)) << 2)];
                k[u][0] = dv.x; k[u][1] = dv.y; k[u][2] = dv.z; k[u][3] = dv.w;
            } else {
                const int cc = t - 128;
                const int cb = cc >> 2, cq = cc & 3;
                #pragma unroll
                for (int q = 0; q < 4; ++q) {
                    const int r = lane + 32 * q;
                    k[u][q] = Dt[r * DPW + (((cb ^ (r & 31)) << 2)
                                 | (cq ^ vlo))];
                }
            }
            sort4u(k[u]);
        }

        uint32_t myk[2];
        #pragma unroll
        for (int pp = 0; pp < 8; ++pp) {
            uint32_t g0 = redux_min_u32(k[0][0]);
            uint32_t g1 = redux_min_u32(k[1][0]);
            if (lane == pp) { myk[0] = g0; myk[1] = g1; }
            if (k[0][0] == g0) {
                k[0][0] = k[0][1]; k[0][1] = k[0][2];
                k[0][2] = k[0][3]; k[0][3] = 0xFFFFFFFFu;
            }
            if (k[1][0] == g1) {
                k[1][0] = k[1][1]; k[1][1] = k[1][2];
                k[1][2] = k[1][3]; k[1][3] = 0xFFFFFFFFu;
            }
        }
        if (lane < 8) {
            #pragma unroll
            for (int u = 0; u < 2; ++u) {
                const int t = t0 + 16 * u;
                const int grow = isrow[u] ? (row0 + t) : (col0 + (t - 128));
                const int slot = isrow[u] ? j : i;
                uint32_t kk = isrow[u] ? myk[u]
                    : ((myk[u] & VMASK) | ((myk[u] >> 7) & 0x7Fu));
                g_pc[(((size_t)(b * HW + grow)) * NSTRIP + slot) * 8 + lane] = kk;
            }
        }
    }
}

// ---------------------------------------------------------------------------
// Kernel 3: warp-per-row merge (pop-min over 32 slot top-8 lists) + exact
// fp32 refinement of 8 candidates + margin flagging.
// ---------------------------------------------------------------------------
__global__ void merge_refine_kernel(const float* __restrict__ x,
                                    float* __restrict__ out, int out_size) {
    int gw   = (blockIdx.x * blockDim.x + threadIdx.x) >> 5;
    int lane = threadIdx.x & 31;
    if (gw >= BATCH * HW) return;
    const int b = gw >> 12, rl = gw & 4095;

    const uint32_t* src = g_pc + ((size_t)gw * NSTRIP + lane) * 8;
    const uint4 lo = *(const uint4*)src;
    const uint4 hi = *(const uint4*)(src + 4);

    // B1 = min over tiles of the tile's 8th-smallest value (lower bound)
    const uint32_t b1 = redux_min_u32(hi.w & VMASK);

    // repack: value | 12-bit global index; lists already sorted ascending
    const uint32_t base = (uint32_t)lane * 128u;
    uint32_t mk[8];
    mk[0] = (lo.x & VMASK) | (base + (lo.x & 0x7Fu));
    mk[1] = (lo.y & VMASK) | (base + (lo.y & 0x7Fu));
    mk[2] = (lo.z & VMASK) | (base + (lo.z & 0x7Fu));
    mk[3] = (lo.w & VMASK) | (base + (lo.w & 0x7Fu));
    mk[4] = (hi.x & VMASK) | (base + (hi.x & 0x7Fu));
    mk[5] = (hi.y & VMASK) | (base + (hi.y & 0x7Fu));
    mk[6] = (hi.z & VMASK) | (base + (hi.z & 0x7Fu));
    mk[7] = (hi.w & VMASK) | (base + (hi.w & 0x7Fu));

    uint32_t gks[8];
    #pragma unroll
    for (int pp = 0; pp < 8; ++pp) {
        uint32_t gv = redux_min_u32(mk[0]);
        gks[pp] = gv;
        if (mk[0] == gv) {
            #pragma unroll
            for (int q = 0; q < 7; ++q) mk[q] = mk[q + 1];
            mk[7] = 0xFFFFFFFFu;
        }
    }

    // exact fp32 refinement: batched partial sums, one interleaved reduction
    const float* xb = x + (size_t)b * HW * CDIM;
    const float* xr = xb + (size_t)rl * CDIM + lane * 8;
    float4 a0 = *(const float4*)xr;
    float4 a1 = *(const float4*)(xr + 4);
    const float nr = g_norms[b * HW + rl];

    float s[8];
    #pragma unroll
    for (int k = 0; k < 8; ++k) {
        const int c = (int)(gks[k] & 0xFFFu);
        const float* xc = xb + (size_t)c * CDIM + lane * 8;
        float4 c0 = *(const float4*)xc;
        float4 c1 = *(const float4*)(xc + 4);
        s[k] = a0.x*c0.x + a0.y*c0.y + a0.z*c0.z + a0.w*c0.w
             + a1.x*c1.x + a1.y*c1.y + a1.z*c1.z + a1.w*c1.w;
    }
    #pragma unroll
    for (int off = 16; off; off >>= 1) {
        #pragma unroll
        for (int k = 0; k < 8; ++k)
            s[k] += __shfl_xor_sync(0xffffffffu, s[k], off);
    }

    float m1 = FLT_MAX, m2 = FLT_MAX; int j1 = 0, j2 = 0;
    #pragma unroll
    for (int k = 0; k < 8; ++k) {
        const int c = (int)(gks[k] & 0xFFFu);
        float D = nr + g_norms[b * HW + c] - 2.f * s[k];
        if (ltp(D, c, m1, j1)) { m2 = m1; j2 = j1; m1 = D; j1 = c; }
        else if (ltp(D, c, m2, j2)) { m2 = D; j2 = c; }
    }

    if (lane == 0) {
        out[(size_t)b * HW + rl] = predict(m1, m2);
        if (out_size >= 2 * BATCH * HW)
            out[(size_t)BATCH * HW + (size_t)b * HW + rl] = (float)j1;
        // bound in x^2 units: key value bits >> 8 = D_int truncated to 64s
        uint32_t bkey = min(b1, gks[7] & VMASK);
        float bound = (float)(bkey >> 8) * (1.0f / (SCALE * SCALE));
        if (m2 > bound - MARGIN) {
            int fi = atomicAdd(&g_flagcnt, 1);
            g_flaglist[fi] = gw;
        }
    }
}

// ---------------------------------------------------------------------------
// Kernel 4: exact full-row rescan for flagged rows (expected ~0 rows).
// ---------------------------------------------------------------------------
__global__ void fallback_kernel(const float* __restrict__ x,
                                float* __restrict__ out, int out_size) {
    __shared__ float sv1[256], sv2[256];
    __shared__ int   si1[256];
    const int n = g_flagcnt;
    for (int fi = blockIdx.x; fi < n; fi += gridDim.x) {
        const int rowg = g_flaglist[fi];
        const int b = rowg >> 12, r = rowg & 4095;
        const float* xb = x + (size_t)b * HW * CDIM;
        const float* xr = xb + (size_t)r * CDIM;
        const float  nr = g_norms[rowg];
        float v1 = FLT_MAX, v2 = FLT_MAX; int i1 = 0x7fffffff;
        for (int c = threadIdx.x; c < HW; c += 256) {
            if (c == r) continue;
            const float4* xc = (const float4*)(xb + (size_t)c * CDIM);
            float s = 0.f;
            #pragma unroll
            for (int d = 0; d < 64; ++d) {
                float4 va = ((const float4*)xr)[d];
                float4 vb = xc[d];
                s += va.x*vb.x + va.y*vb.y + va.z*vb.z + va.w*vb.w;
            }
            float D = nr + g_norms[b * HW + c] - 2.f * s;
            if (ltp(D, c, v1, i1)) { v2 = v1; v1 = D; i1 = c; }
            else if (D < v2) { v2 = D; }
        }
        sv1[threadIdx.x] = v1; sv2[threadIdx.x] = v2; si1[threadIdx.x] = i1;
        __syncthreads();
        for (int off = 128; off; off >>= 1) {
            if (threadIdx.x < off) {
                float b1 = sv1[threadIdx.x + off], b2 = sv2[threadIdx.x + off];
                int   bi = si1[threadIdx.x + off];
                float a1v = sv1[threadIdx.x]; int a1i = si1[threadIdx.x];
                if (ltp(b1, bi, a1v, a1i)) {
                    sv2[threadIdx.x] = fminf(a1v, b2);
                    sv1[threadIdx.x] = b1; si1[threadIdx.x] = bi;
                } else {
                    sv2[threadIdx.x] = fminf(sv2[threadIdx.x], b1);
                }
            }
            __syncthreads();
        }
        if (threadIdx.x == 0) {
            out[(size_t)b * HW + r] = predict(sv1[0], sv2[0]);
            if (out_size >= 2 * BATCH * HW)
                out[(size_t)BATCH * HW + (size_t)b * HW + r] = (float)si1[0];
        }
        __syncthreads();
    }
}

// ---------------------------------------------------------------------------
extern "C" void kernel_launch(void* const* d_in, const int* in_sizes, int n_in,
                              void* d_out, int out_size) {
    const float* x   = (const float*)d_in[0];
    float*       out = (float*)d_out;

    convert_norms_kernel<<<BATCH * HW / 16, 256>>>(x);

    cudaFuncSetAttribute(fcm_pair_kernel,
                         cudaFuncAttributeMaxDynamicSharedMemorySize, TOTSMEM);
    dim3 grid(NPAIR, BATCH);
    fcm_pair_kernel<<<grid, 512, TOTSMEM>>>();

    merge_refine_kernel<<<BATCH * HW / 8, 256>>>(x, out, out_size);
    fallback_kernel<<<64, 256>>>(x, out, out_size);
}